// round 16
// baseline (speedup 1.0000x reference)
#include <cuda_runtime.h>
#include <math.h>

#define N_OBS   256
#define N_Y     128
#define N_X     64
#define NITERS  150
#define NTHREADS 320        // 8 matrix warps (4 X + 4 Y) + 2 projector warps
#define MWARPS   8
#define ZCNT     160        // z-barrier: 4 matrix warps (sync) + projector (arrive)
#define DCNT     288        // data barrier: 8 matrix warps (arrive) + projector (sync)

__device__ float g_ep[N_OBS * N_Y];             // ep row-major [t][j]
__device__ float g_yhat_fallback[N_OBS * N_Y];

// ---- packed f32x2 helpers (sm_103a) ---------------------------------------
typedef unsigned long long u64;
__device__ __forceinline__ void fma2(u64& d, u64 a, u64 b) {
    asm("fma.rn.f32x2 %0, %1, %2, %0;" : "+l"(d) : "l"(a), "l"(b));
}
__device__ __forceinline__ void add2(u64& d, u64 a) {
    asm("add.rn.f32x2 %0, %0, %1;" : "+l"(d) : "l"(a));
}
__device__ __forceinline__ u64 pk2(float lo, float hi) {
    u64 r;
    asm("mov.b64 %0, {%1, %2};" : "=l"(r) : "f"(lo), "f"(hi));
    return r;
}
__device__ __forceinline__ float upk_lo(u64 v) {
    float lo, hi; asm("mov.b64 {%0, %1}, %2;" : "=f"(lo), "=f"(hi) : "l"(v)); return lo;
}
__device__ __forceinline__ float upk_hi(u64 v) {
    float lo, hi; asm("mov.b64 {%0, %1}, %2;" : "=f"(lo), "=f"(hi) : "l"(v)); return hi;
}
__device__ __forceinline__ float upk_sum(u64 v) {
    float lo, hi; asm("mov.b64 {%0, %1}, %2;" : "=f"(lo), "=f"(hi) : "l"(v)); return lo + hi;
}

// ---- named barriers (runtime id/count) -------------------------------------
__device__ __forceinline__ void nbar_sync(int id, int cnt) {
    asm volatile("bar.sync %0, %1;" :: "r"(id), "r"(cnt) : "memory");
}
__device__ __forceinline__ void nbar_arrive(int id, int cnt) {
    asm volatile("bar.arrive %0, %1;" :: "r"(id), "r"(cnt) : "memory");
}

// ---------------------------------------------------------------------------
// Kernel 1: Y_hat = X @ W^T + b ; ep = Y - Y_hat (row-major)
// ---------------------------------------------------------------------------
__global__ void prep_kernel(const float* __restrict__ X,
                            const float* __restrict__ Y,
                            const float* __restrict__ W,
                            const float* __restrict__ b,
                            float* __restrict__ yhat_out) {
    __shared__ float Xs[N_X];
    __shared__ float Ws[N_Y * (N_X + 1)];
    const int t = blockIdx.x;
    const int i = threadIdx.x;

    if (i < N_X) Xs[i] = X[t * N_X + i];
    for (int idx = i; idx < N_Y * N_X; idx += blockDim.x) {
        int r = idx >> 6, cx = idx & 63;
        Ws[r * (N_X + 1) + cx] = W[idx];
    }
    __syncthreads();

    float acc = b[i];
#pragma unroll
    for (int x = 0; x < N_X; x++) acc += Xs[x] * Ws[i * (N_X + 1) + x];

    yhat_out[t * N_Y + i] = acc;
    g_ep[t * N_Y + i] = Y[t * N_Y + i] - acc;
}

// ---------------------------------------------------------------------------
// Block-layout warp-local simplex projection: sums 8 per-warp partials,
// v = z - lr*(g - gamma*yh), z = proj_simplex(v). i = lane*4 + r.
// ---------------------------------------------------------------------------
__device__ __forceinline__ void cswap(float& a, float& b, bool asc) {
    const float lo = fminf(a, b), hi = fmaxf(a, b);
    a = asc ? lo : hi;
    b = asc ? hi : lo;
}

__device__ __forceinline__ void project_warp8(const float* __restrict__ part,
                                              const float* __restrict__ yh,
                                              float* __restrict__ zz,
                                              float lr, float gamma) {
    const unsigned FULL = 0xffffffffu;
    const int lane = threadIdx.x & 31;

    float g0 = 0.0f, g1 = 0.0f, g2 = 0.0f, g3 = 0.0f;
#pragma unroll
    for (int w = 0; w < MWARPS; w++) {
        const float4 p = *reinterpret_cast<const float4*>(&part[w * N_Y + lane * 4]);
        g0 += p.x; g1 += p.y; g2 += p.z; g3 += p.w;
    }
    const float4 yv = *reinterpret_cast<const float4*>(&yh[lane * 4]);
    const float4 zv = *reinterpret_cast<const float4*>(&zz[lane * 4]);

    float vorig[4], val[4];
    vorig[0] = zv.x - lr * (g0 - gamma * yv.x);
    vorig[1] = zv.y - lr * (g1 - gamma * yv.y);
    vorig[2] = zv.z - lr * (g2 - gamma * yv.z);
    vorig[3] = zv.w - lr * (g3 - gamma * yv.w);
#pragma unroll
    for (int r = 0; r < 4; r++) val[r] = vorig[r];

    cswap(val[0], val[1], true);
    cswap(val[2], val[3], false);
    {
        const bool a = (lane & 1) == 0;
        cswap(val[0], val[2], a); cswap(val[1], val[3], a);
        cswap(val[0], val[1], a); cswap(val[2], val[3], a);
    }

#define SHFL_LEVEL(ls, asc) do {                                         \
        const bool _low = (lane & (ls)) == 0;                            \
        _Pragma("unroll")                                                \
        for (int r = 0; r < 4; r++) {                                    \
            const float pv = __shfl_xor_sync(FULL, val[r], (ls));        \
            val[r] = (_low == (asc)) ? fminf(val[r], pv)                 \
                                     : fmaxf(val[r], pv);                \
        }                                                                \
    } while (0)

#define REG_TAIL(asc) do {                                               \
        cswap(val[0], val[2], (asc)); cswap(val[1], val[3], (asc));      \
        cswap(val[0], val[1], (asc)); cswap(val[2], val[3], (asc));      \
    } while (0)

    { const bool a = (lane & 2)  == 0; SHFL_LEVEL(1, a); REG_TAIL(a); }
    { const bool a = (lane & 4)  == 0; SHFL_LEVEL(2, a); SHFL_LEVEL(1, a); REG_TAIL(a); }
    { const bool a = (lane & 8)  == 0; SHFL_LEVEL(4, a); SHFL_LEVEL(2, a); SHFL_LEVEL(1, a); REG_TAIL(a);}
    { const bool a = (lane & 16) == 0; SHFL_LEVEL(8, a); SHFL_LEVEL(4, a); SHFL_LEVEL(2, a);
      SHFL_LEVEL(1, a); REG_TAIL(a); }
    { SHFL_LEVEL(16, true); SHFL_LEVEL(8, true); SHFL_LEVEL(4, true); SHFL_LEVEL(2, true);
      SHFL_LEVEL(1, true); REG_TAIL(true); }

#undef SHFL_LEVEL
#undef REG_TAIL

    const float s0 = val[0];
    const float s1 = s0 + val[1];
    const float s2 = s1 + val[2];
    const float s3 = s2 + val[3];
    float incl = s3;
#pragma unroll
    for (int d = 1; d < 32; d <<= 1) {
        const float y = __shfl_up_sync(FULL, incl, d);
        if (lane >= d) incl += y;
    }
    const float prefix = incl - s3;
    const float Stot = __shfl_sync(FULL, incl, 31);
    const float P[4] = { s0 + prefix, s1 + prefix, s2 + prefix, s3 + prefix };

    int rho = 0;
    float cssr[4];
#pragma unroll
    for (int r = 0; r < 4; r++) {
        const int i = lane * 4 + r;
        const float css = Stot - P[r] + val[r];
        cssr[r] = css;
        const bool cond = (val[r] + (1.0f - css) / (float)(128 - i)) > 0.0f;
        rho += __popc(__ballot_sync(FULL, cond));
    }

    const int it = 128 - rho;
    const int Lt = it >> 2, rt = it & 3;
    const float sel = (rt == 0) ? cssr[0] : (rt == 1) ? cssr[1]
                    : (rt == 2) ? cssr[2] : cssr[3];
    const float css_t = __shfl_sync(FULL, sel, Lt);
    const float theta = (css_t - 1.0f) / (float)rho;

    float4 zo;
    zo.x = fmaxf(vorig[0] - theta, 0.0f);
    zo.y = fmaxf(vorig[1] - theta, 0.0f);
    zo.z = fmaxf(vorig[2] - theta, 0.0f);
    zo.w = fmaxf(vorig[3] - theta, 0.0f);
    *reinterpret_cast<float4*>(&zz[lane * 4]) = zo;
}

// ---------------------------------------------------------------------------
// Matrix-warp work for ONE scenario (identical math to R14's passing version):
// sync(z-ready), dot+fused butterfly -> r_t, indicator/w, red sums, g_z
// partial, FENCE, arrive(data-ready). Lane L holds r for row 32*wid + L.
// ---------------------------------------------------------------------------
__device__ __forceinline__ void mat_scenario(const u64* __restrict__ epB,
                                             const float* __restrict__ zz,
                                             const float* __restrict__ sc,
                                             float* __restrict__ redI,
                                             float* __restrict__ redW,
                                             float* __restrict__ part,
                                             int lane, int wid,
                                             int zbar, int dbar) {
    const unsigned FULL = 0xffffffffu;
    nbar_sync(zbar, ZCNT);
    const float c = sc[0], eta = sc[1], lam = sc[2];
    const float4 zv = *reinterpret_cast<const float4*>(&zz[4 * lane]);
    const u64 z0 = pk2(zv.x, zv.y), z1 = pk2(zv.z, zv.w);

    const bool hi16 = (lane & 16) != 0;
    const bool hi8  = (lane & 8) != 0;
    float q[8];
#pragma unroll
    for (int i = 0; i < 8; i++) {
        u64 a0 = 0, a1 = 0, a2 = 0, a3 = 0;
        fma2(a0, epB[2 * i],            z0); fma2(a0, epB[2 * i + 1],            z1);
        fma2(a1, epB[2 * (i + 8)],      z0); fma2(a1, epB[2 * (i + 8) + 1],      z1);
        fma2(a2, epB[2 * (i + 16)],     z0); fma2(a2, epB[2 * (i + 16) + 1],     z1);
        fma2(a3, epB[2 * (i + 24)],     z0); fma2(a3, epB[2 * (i + 24) + 1],     z1);
        const float p0  = upk_sum(a0);
        const float p8  = upk_sum(a1);
        const float p16 = upk_sum(a2);
        const float p24 = upk_sum(a3);
        float ka = hi16 ? p16 : p0;
        const float sa = hi16 ? p0 : p16;
        ka += __shfl_xor_sync(FULL, sa, 16);
        float kb = hi16 ? p24 : p8;
        const float sb = hi16 ? p8 : p24;
        kb += __shfl_xor_sync(FULL, sb, 16);
        const float kc = hi8 ? kb : ka;
        const float sc2 = hi8 ? ka : kb;
        q[i] = kc + __shfl_xor_sync(FULL, sc2, 8);
    }
#pragma unroll
    for (int d = 4; d >= 1; d >>= 1) {
        const bool hi = (lane & d) != 0;
#pragma unroll
        for (int i = 0; i < d; i++) {
            const float keep = hi ? q[i + d] : q[i];
            const float send = hi ? q[i] : q[i + d];
            q[i] = keep + __shfl_xor_sync(FULL, send, d);
        }
    }
    const float r = q[0] - c;             // row 32*wid + lane
    const float av = r * r - eta;
    const float I = (av > -lam) ? 1.0f : ((av < -lam) ? 0.0f : 0.5f);
    const float w = I * 2.0f * r * (1.0f / (float)N_OBS);

    u64 s = pk2(I, w);
#pragma unroll
    for (int d = 16; d >= 1; d >>= 1) add2(s, __shfl_xor_sync(FULL, s, d));
    if (lane == 0) { redI[wid] = upk_lo(s); redW[wid] = upk_hi(s); }

    u64 g0 = 0, g1 = 0;
#pragma unroll
    for (int tt = 0; tt < 32; tt++) {
        const float wt = __shfl_sync(FULL, w, tt);
        const u64 wp = pk2(wt, wt);
        fma2(g0, epB[2 * tt],     wp);
        fma2(g1, epB[2 * tt + 1], wp);
    }
    float4 o;
    o.x = upk_lo(g0); o.y = upk_hi(g0); o.z = upk_lo(g1); o.w = upk_hi(g1);
    *reinterpret_cast<float4*>(&part[wid * N_Y + 4 * lane]) = o;
    __threadfence_block();     // drain STS before arrive (bar.arrive doesn't)
    nbar_arrive(dbar, DCNT);
}

// ---------------------------------------------------------------------------
// Kernel 2: phase-offset dual groups. Warps 0-3 (X): scenario A then B.
// Warps 4-7 (Y): scenario B then A. Warp 8: projector A; warp 9: projector B.
// Each SMSP hosts one X warp + one Y warp in OPPOSITE pipeline phases.
// Barriers: 1=zA ready for X, 5=zA ready for Y, 2=A data (shared)
//           3=zB ready for X, 7=zB ready for Y, 4=B data (shared)
// ---------------------------------------------------------------------------
__global__ __launch_bounds__(NTHREADS, 1)
void solver_kernel(const float* __restrict__ yhat_all,
                   const float* __restrict__ delta_p,
                   const float* __restrict__ gamma_p,
                   float* __restrict__ zout) {
    __shared__ float zA[N_Y], zB[N_Y];
    __shared__ float yhA[N_Y], yhB[N_Y];
    __shared__ float partA[MWARPS * N_Y], partB[MWARPS * N_Y];
    __shared__ float redIA[MWARPS], redWA[MWARPS], redIB[MWARPS], redWB[MWARPS];
    __shared__ float scA[3], scB[3];   // c, eta, lam

    const int tid  = threadIdx.x;
    const int lane = tid & 31;
    const int wid  = tid >> 5;
    const int sA = blockIdx.x * 2;
    const int sB = sA + 1;
    const float delta = *delta_p;
    const float gamma = *gamma_p;

    if (tid < N_Y) {
        zA[tid] = 1.0f / (float)N_Y;
        zB[tid] = 1.0f / (float)N_Y;
        yhA[tid] = yhat_all[sA * N_Y + tid];
        yhB[tid] = yhat_all[sB * N_Y + tid];
    }
    if (tid == 0) { scA[0] = 0.0f; scA[1] = 0.0f; scA[2] = 0.1f;
                    scB[0] = 0.0f; scB[1] = 0.0f; scB[2] = 0.1f; }

    u64 epB[64];                 // 32 rows per matrix warp (R14 layout)
    if (wid < MWARPS) {
#pragma unroll
        for (int tt = 0; tt < 32; tt++) {
            const float4 e = *reinterpret_cast<const float4*>(
                &g_ep[(32 * wid + tt) * N_Y + 4 * lane]);
            epB[2 * tt]     = pk2(e.x, e.y);
            epB[2 * tt + 1] = pk2(e.z, e.w);
        }
    }
    __syncthreads();

    if (wid < 4) {
        // ---- group X: A then B ----
        for (int k = 0; k < NITERS; k++) {
            mat_scenario(epB, zA, scA, redIA, redWA, partA, lane, wid, 1, 2);
            mat_scenario(epB, zB, scB, redIB, redWB, partB, lane, wid, 3, 4);
        }
    } else if (wid < MWARPS) {
        // ---- group Y: B then A (half-iteration phase offset) ----
        for (int k = 0; k < NITERS; k++) {
            mat_scenario(epB, zB, scB, redIB, redWB, partB, lane, wid, 7, 4);
            mat_scenario(epB, zA, scA, redIA, redWA, partA, lane, wid, 5, 2);
        }
    } else if (wid == MWARPS) {
        // ---- projector A ----
        float c = 0.0f, eta = 0.0f, lam = 0.1f;
        for (int k = 0; k < NITERS; k++) {
            const float lr = 0.05f / sqrtf(1.0f + (float)k);
            __threadfence_block();         // drain z/sc writes before publish
            nbar_arrive(1, ZCNT);          // publish zA_k to X
            nbar_arrive(5, ZCNT);          // publish zA_k to Y
            nbar_sync(2, DCNT);            // wait all A data (X early, Y late)
            float SI = 0.0f, SW = 0.0f;
#pragma unroll
            for (int i = 0; i < MWARPS; i++) { SI += redIA[i]; SW += redWA[i]; }
            c   += lr * SW;
            eta -= lr * (1.0f - SI * (1.0f / (float)N_OBS));
            lam  = fmaxf(lam - lr * (delta - 1.0f + SI * (1.0f / (float)N_OBS)), 0.0f);
            if (lane == 0) { scA[0] = c; scA[1] = eta; scA[2] = lam; }
            project_warp8(partA, yhA, zA, lr, gamma);
        }
    } else {
        // ---- projector B ----
        float c = 0.0f, eta = 0.0f, lam = 0.1f;
        for (int k = 0; k < NITERS; k++) {
            const float lr = 0.05f / sqrtf(1.0f + (float)k);
            __threadfence_block();
            nbar_arrive(3, ZCNT);          // publish zB_k to X
            nbar_arrive(7, ZCNT);          // publish zB_k to Y
            nbar_sync(4, DCNT);            // wait all B data (Y early, X late)
            float SI = 0.0f, SW = 0.0f;
#pragma unroll
            for (int i = 0; i < MWARPS; i++) { SI += redIB[i]; SW += redWB[i]; }
            c   += lr * SW;
            eta -= lr * (1.0f - SI * (1.0f / (float)N_OBS));
            lam  = fmaxf(lam - lr * (delta - 1.0f + SI * (1.0f / (float)N_OBS)), 0.0f);
            if (lane == 0) { scB[0] = c; scB[1] = eta; scB[2] = lam; }
            project_warp8(partB, yhB, zB, lr, gamma);
        }
    }
    __syncthreads();

    if (tid < 128) {
        zout[sA * N_Y + tid] = zA[tid];
    } else if (tid < 256) {
        zout[sB * N_Y + (tid - 128)] = zB[tid - 128];
    }
}

// ---------------------------------------------------------------------------
extern "C" void kernel_launch(void* const* d_in, const int* in_sizes, int n_in,
                              void* d_out, int out_size) {
    const float* X     = (const float*)d_in[0];
    const float* Y     = (const float*)d_in[1];
    const float* W     = (const float*)d_in[2];
    const float* b     = (const float*)d_in[3];
    const float* delta = (const float*)d_in[4];
    const float* gamma = (const float*)d_in[5];

    float* out = (float*)d_out;
    float* zout = out;
    float* yhat;
    if (out_size >= 2 * N_OBS * N_Y) {
        yhat = out + N_OBS * N_Y;
    } else {
        void* p = nullptr;
        cudaGetSymbolAddress(&p, g_yhat_fallback);
        yhat = (float*)p;
    }

    prep_kernel<<<N_OBS, N_Y>>>(X, Y, W, b, yhat);
    solver_kernel<<<N_OBS / 2, NTHREADS>>>(yhat, delta, gamma, zout);
}

// round 17
// speedup vs baseline: 1.1988x; 1.1988x over previous
#include <cuda_runtime.h>
#include <math.h>

#define N_OBS   256
#define N_Y     128
#define N_X     64
#define NITERS  150
#define NTHREADS 320        // 8 matrix warps + 2 projector warps
#define MWARPS   8
#define BARCNT   288        // 256 matrix threads + 32 projector threads

__device__ float g_ep[N_OBS * N_Y];             // ep row-major [t][j]
__device__ float g_yhat_fallback[N_OBS * N_Y];

// ---- packed f32x2 helpers (sm_103a) ---------------------------------------
typedef unsigned long long u64;
__device__ __forceinline__ void fma2(u64& d, u64 a, u64 b) {
    asm("fma.rn.f32x2 %0, %1, %2, %0;" : "+l"(d) : "l"(a), "l"(b));
}
__device__ __forceinline__ void add2(u64& d, u64 a) {
    asm("add.rn.f32x2 %0, %0, %1;" : "+l"(d) : "l"(a));
}
__device__ __forceinline__ u64 pk2(float lo, float hi) {
    u64 r;
    asm("mov.b64 %0, {%1, %2};" : "=l"(r) : "f"(lo), "f"(hi));
    return r;
}
__device__ __forceinline__ float upk_lo(u64 v) {
    float lo, hi; asm("mov.b64 {%0, %1}, %2;" : "=f"(lo), "=f"(hi) : "l"(v)); return lo;
}
__device__ __forceinline__ float upk_hi(u64 v) {
    float lo, hi; asm("mov.b64 {%0, %1}, %2;" : "=f"(lo), "=f"(hi) : "l"(v)); return hi;
}
__device__ __forceinline__ float upk_sum(u64 v) {
    float lo, hi; asm("mov.b64 {%0, %1}, %2;" : "=f"(lo), "=f"(hi) : "l"(v)); return lo + hi;
}

// ---- named barriers ---------------------------------------------------------
__device__ __forceinline__ void nbar_sync(int id) {
    asm volatile("bar.sync %0, %1;" :: "r"(id), "r"(BARCNT) : "memory");
}
__device__ __forceinline__ void nbar_arrive(int id) {
    asm volatile("bar.arrive %0, %1;" :: "r"(id), "r"(BARCNT) : "memory");
}

// ---------------------------------------------------------------------------
// Kernel 1: Y_hat = X @ W^T + b ; ep = Y - Y_hat (row-major)
// ---------------------------------------------------------------------------
__global__ void prep_kernel(const float* __restrict__ X,
                            const float* __restrict__ Y,
                            const float* __restrict__ W,
                            const float* __restrict__ b,
                            float* __restrict__ yhat_out) {
    __shared__ float Xs[N_X];
    __shared__ float Ws[N_Y * (N_X + 1)];
    const int t = blockIdx.x;
    const int i = threadIdx.x;

    if (i < N_X) Xs[i] = X[t * N_X + i];
    for (int idx = i; idx < N_Y * N_X; idx += blockDim.x) {
        int r = idx >> 6, cx = idx & 63;
        Ws[r * (N_X + 1) + cx] = W[idx];
    }
    __syncthreads();

    float acc = b[i];
#pragma unroll
    for (int x = 0; x < N_X; x++) acc += Xs[x] * Ws[i * (N_X + 1) + x];

    yhat_out[t * N_Y + i] = acc;
    g_ep[t * N_Y + i] = Y[t * N_Y + i] - acc;
}

// ---------------------------------------------------------------------------
// Block-layout warp-local simplex projection: sums 8 per-warp partials,
// v = z - lr*(g - gamma*yh), z = proj_simplex(v). i = lane*4 + r.
// ---------------------------------------------------------------------------
__device__ __forceinline__ void cswap(float& a, float& b, bool asc) {
    const float lo = fminf(a, b), hi = fmaxf(a, b);
    a = asc ? lo : hi;
    b = asc ? hi : lo;
}

__device__ __forceinline__ void project_warp8(const float* __restrict__ part,
                                              const float* __restrict__ yh,
                                              float* __restrict__ zz,
                                              float lr, float gamma) {
    const unsigned FULL = 0xffffffffu;
    const int lane = threadIdx.x & 31;

    float g0 = 0.0f, g1 = 0.0f, g2 = 0.0f, g3 = 0.0f;
#pragma unroll
    for (int w = 0; w < MWARPS; w++) {
        const float4 p = *reinterpret_cast<const float4*>(&part[w * N_Y + lane * 4]);
        g0 += p.x; g1 += p.y; g2 += p.z; g3 += p.w;
    }
    const float4 yv = *reinterpret_cast<const float4*>(&yh[lane * 4]);
    const float4 zv = *reinterpret_cast<const float4*>(&zz[lane * 4]);

    float vorig[4], val[4];
    vorig[0] = zv.x - lr * (g0 - gamma * yv.x);
    vorig[1] = zv.y - lr * (g1 - gamma * yv.y);
    vorig[2] = zv.z - lr * (g2 - gamma * yv.z);
    vorig[3] = zv.w - lr * (g3 - gamma * yv.w);
#pragma unroll
    for (int r = 0; r < 4; r++) val[r] = vorig[r];

    cswap(val[0], val[1], true);
    cswap(val[2], val[3], false);
    {
        const bool a = (lane & 1) == 0;
        cswap(val[0], val[2], a); cswap(val[1], val[3], a);
        cswap(val[0], val[1], a); cswap(val[2], val[3], a);
    }

#define SHFL_LEVEL(ls, asc) do {                                         \
        const bool _low = (lane & (ls)) == 0;                            \
        _Pragma("unroll")                                                \
        for (int r = 0; r < 4; r++) {                                    \
            const float pv = __shfl_xor_sync(FULL, val[r], (ls));        \
            val[r] = (_low == (asc)) ? fminf(val[r], pv)                 \
                                     : fmaxf(val[r], pv);                \
        }                                                                \
    } while (0)

#define REG_TAIL(asc) do {                                               \
        cswap(val[0], val[2], (asc)); cswap(val[1], val[3], (asc));      \
        cswap(val[0], val[1], (asc)); cswap(val[2], val[3], (asc));      \
    } while (0)

    { const bool a = (lane & 2)  == 0; SHFL_LEVEL(1, a); REG_TAIL(a); }
    { const bool a = (lane & 4)  == 0; SHFL_LEVEL(2, a); SHFL_LEVEL(1, a); REG_TAIL(a); }
    { const bool a = (lane & 8)  == 0; SHFL_LEVEL(4, a); SHFL_LEVEL(2, a); SHFL_LEVEL(1, a); REG_TAIL(a);}
    { const bool a = (lane & 16) == 0; SHFL_LEVEL(8, a); SHFL_LEVEL(4, a); SHFL_LEVEL(2, a);
      SHFL_LEVEL(1, a); REG_TAIL(a); }
    { SHFL_LEVEL(16, true); SHFL_LEVEL(8, true); SHFL_LEVEL(4, true); SHFL_LEVEL(2, true);
      SHFL_LEVEL(1, true); REG_TAIL(true); }

#undef SHFL_LEVEL
#undef REG_TAIL

    const float s0 = val[0];
    const float s1 = s0 + val[1];
    const float s2 = s1 + val[2];
    const float s3 = s2 + val[3];
    float incl = s3;
#pragma unroll
    for (int d = 1; d < 32; d <<= 1) {
        const float y = __shfl_up_sync(FULL, incl, d);
        if (lane >= d) incl += y;
    }
    const float prefix = incl - s3;
    const float Stot = __shfl_sync(FULL, incl, 31);
    const float P[4] = { s0 + prefix, s1 + prefix, s2 + prefix, s3 + prefix };

    int rho = 0;
    float cssr[4];
#pragma unroll
    for (int r = 0; r < 4; r++) {
        const int i = lane * 4 + r;
        const float css = Stot - P[r] + val[r];
        cssr[r] = css;
        const bool cond = (val[r] + (1.0f - css) / (float)(128 - i)) > 0.0f;
        rho += __popc(__ballot_sync(FULL, cond));
    }

    const int it = 128 - rho;
    const int Lt = it >> 2, rt = it & 3;
    const float sel = (rt == 0) ? cssr[0] : (rt == 1) ? cssr[1]
                    : (rt == 2) ? cssr[2] : cssr[3];
    const float css_t = __shfl_sync(FULL, sel, Lt);
    const float theta = (css_t - 1.0f) / (float)rho;

    float4 zo;
    zo.x = fmaxf(vorig[0] - theta, 0.0f);
    zo.y = fmaxf(vorig[1] - theta, 0.0f);
    zo.z = fmaxf(vorig[2] - theta, 0.0f);
    zo.w = fmaxf(vorig[3] - theta, 0.0f);
    *reinterpret_cast<float4*>(&zz[lane * 4]) = zo;
}

// ---------------------------------------------------------------------------
// Matrix-warp work for ONE scenario with ROW-PAIR packed registers:
// epP[4i+s] = (ep[32*wid+i][4*lane+s], ep[32*wid+i+16][4*lane+s]), i=0..15.
// Dot phase: z splats -> each fma2 advances BOTH rows' dots (no horizontal
// unpacks). Transpose-reduce: fused d=8 level + d=4,2,1 + bit-16 fold
// (u64 shfls). Lane L takes lo (L<16) / hi (L>=16) => r for row 32*wid+L.
// (I,w) published to wIall for the projector (scalar sums offloaded).
// ---------------------------------------------------------------------------
__device__ __forceinline__ void mat_scenario(const u64* __restrict__ epP,
                                             const float* __restrict__ zz,
                                             const float* __restrict__ sc,
                                             u64* __restrict__ wIall,
                                             float* __restrict__ part,
                                             int lane, int wid,
                                             int zbar, int dbar) {
    const unsigned FULL = 0xffffffffu;
    nbar_sync(zbar);
    const float c = sc[0], eta = sc[1], lam = sc[2];
    const float4 zv = *reinterpret_cast<const float4*>(&zz[4 * lane]);
    const u64 zs0 = pk2(zv.x, zv.x), zs1 = pk2(zv.y, zv.y);
    const u64 zs2 = pk2(zv.z, zv.z), zs3 = pk2(zv.w, zv.w);

    const bool hi8 = (lane & 8) != 0;
    u64 q[8];
#pragma unroll
    for (int i = 0; i < 8; i++) {
        u64 a = 0, b = 0;
        fma2(a, epP[4 * i + 0],       zs0);
        fma2(a, epP[4 * i + 1],       zs1);
        fma2(a, epP[4 * i + 2],       zs2);
        fma2(a, epP[4 * i + 3],       zs3);
        fma2(b, epP[4 * (i + 8) + 0], zs0);
        fma2(b, epP[4 * (i + 8) + 1], zs1);
        fma2(b, epP[4 * (i + 8) + 2], zs2);
        fma2(b, epP[4 * (i + 8) + 3], zs3);
        u64 keep = hi8 ? b : a;
        const u64 send = hi8 ? a : b;
        add2(keep, __shfl_xor_sync(FULL, send, 8));
        q[i] = keep;
    }
#pragma unroll
    for (int d = 4; d >= 1; d >>= 1) {
        const bool hi = (lane & d) != 0;
#pragma unroll
        for (int i = 0; i < d; i++) {
            u64 keep = hi ? q[i + d] : q[i];
            const u64 send = hi ? q[i] : q[i + d];
            add2(keep, __shfl_xor_sync(FULL, send, d));
            q[i] = keep;
        }
    }
    add2(q[0], __shfl_xor_sync(FULL, q[0], 16));   // fold lane bit 4

    const float r = ((lane & 16) ? upk_hi(q[0]) : upk_lo(q[0])) - c;  // row 32*wid+lane
    const float av = r * r - eta;
    const float I = (av > -lam) ? 1.0f : ((av < -lam) ? 0.0f : 0.5f);
    const float w = I * 2.0f * r * (1.0f / (float)N_OBS);

    wIall[32 * wid + lane] = pk2(I, w);   // projector sums these

    // Phase B: g partial over own 32 rows; wpair = (w_i, w_{i+16})
    u64 g0 = 0, g1 = 0, g2 = 0, g3 = 0;
#pragma unroll
    for (int i = 0; i < 16; i++) {
        const u64 wp = pk2(__shfl_sync(FULL, w, i),
                           __shfl_sync(FULL, w, i + 16));
        fma2(g0, epP[4 * i + 0], wp);
        fma2(g1, epP[4 * i + 1], wp);
        fma2(g2, epP[4 * i + 2], wp);
        fma2(g3, epP[4 * i + 3], wp);
    }
    float4 o;
    o.x = upk_sum(g0); o.y = upk_sum(g1); o.z = upk_sum(g2); o.w = upk_sum(g3);
    *reinterpret_cast<float4*>(&part[wid * N_Y + 4 * lane]) = o;
    nbar_arrive(dbar);
}

// ---------------------------------------------------------------------------
// Kernel 2: R14 skeleton (champion): 8 matrix warps process A then B;
// warp 8 projects A, warp 9 projects B (each owns its scalars in regs and
// now also sums (I,w) from wIall). Named barriers: 1=zA,2=dataA,3=zB,4=dataB.
// ---------------------------------------------------------------------------
__global__ __launch_bounds__(NTHREADS, 1)
void solver_kernel(const float* __restrict__ yhat_all,
                   const float* __restrict__ delta_p,
                   const float* __restrict__ gamma_p,
                   float* __restrict__ zout) {
    __shared__ float zA[N_Y], zB[N_Y];
    __shared__ float yhA[N_Y], yhB[N_Y];
    __shared__ float partA[MWARPS * N_Y], partB[MWARPS * N_Y];
    __shared__ u64 wIA[N_OBS], wIB[N_OBS];
    __shared__ float scA[3], scB[3];   // c, eta, lam

    const int tid  = threadIdx.x;
    const int lane = tid & 31;
    const int wid  = tid >> 5;
    const int sA = blockIdx.x * 2;
    const int sB = sA + 1;
    const float delta = *delta_p;
    const float gamma = *gamma_p;
    const unsigned FULL = 0xffffffffu;

    if (tid < N_Y) {
        zA[tid] = 1.0f / (float)N_Y;
        zB[tid] = 1.0f / (float)N_Y;
        yhA[tid] = yhat_all[sA * N_Y + tid];
        yhB[tid] = yhat_all[sB * N_Y + tid];
    }
    if (tid == 0) { scA[0] = 0.0f; scA[1] = 0.0f; scA[2] = 0.1f;
                    scB[0] = 0.0f; scB[1] = 0.0f; scB[2] = 0.1f; }

    // Row-pair packed register matrix: epP[4i+s] = (row 32w+i, row 32w+i+16)
    // at column 4*lane+s.
    u64 epP[64];
    if (wid < MWARPS) {
#pragma unroll
        for (int i = 0; i < 16; i++) {
            const float4 e0 = *reinterpret_cast<const float4*>(
                &g_ep[(32 * wid + i) * N_Y + 4 * lane]);
            const float4 e1 = *reinterpret_cast<const float4*>(
                &g_ep[(32 * wid + i + 16) * N_Y + 4 * lane]);
            epP[4 * i + 0] = pk2(e0.x, e1.x);
            epP[4 * i + 1] = pk2(e0.y, e1.y);
            epP[4 * i + 2] = pk2(e0.z, e1.z);
            epP[4 * i + 3] = pk2(e0.w, e1.w);
        }
    }
    __syncthreads();

    if (wid < MWARPS) {
        // ---- matrix warps: A then B each iteration ----
        for (int k = 0; k < NITERS; k++) {
            mat_scenario(epP, zA, scA, wIA, partA, lane, wid, 1, 2);
            mat_scenario(epP, zB, scB, wIB, partB, lane, wid, 3, 4);
        }
    } else if (wid == MWARPS) {
        // ---- projector A (owns c/eta/lam in registers) ----
        float c = 0.0f, eta = 0.0f, lam = 0.1f;
        for (int k = 0; k < NITERS; k++) {
            const float lr = 0.05f / sqrtf(1.0f + (float)k);
            nbar_arrive(1);        // publish zA_k + scalars_k
            nbar_sync(2);          // wait matrix data
            // sum (I, w) over all 256 rows
            u64 s = 0;
            {
                const ulonglong2* wv =
                    reinterpret_cast<const ulonglong2*>(&wIA[lane * 8]);
#pragma unroll
                for (int kk = 0; kk < 4; kk++) {
                    const ulonglong2 v = wv[kk];
                    add2(s, v.x);
                    add2(s, v.y);
                }
#pragma unroll
                for (int d = 16; d >= 1; d >>= 1)
                    add2(s, __shfl_xor_sync(FULL, s, d));
            }
            const float SI = upk_lo(s), SW = upk_hi(s);
            c   += lr * SW;
            eta -= lr * (1.0f - SI * (1.0f / (float)N_OBS));
            lam  = fmaxf(lam - lr * (delta - 1.0f + SI * (1.0f / (float)N_OBS)), 0.0f);
            if (lane == 0) { scA[0] = c; scA[1] = eta; scA[2] = lam; }
            project_warp8(partA, yhA, zA, lr, gamma);
        }
    } else {
        // ---- projector B ----
        float c = 0.0f, eta = 0.0f, lam = 0.1f;
        for (int k = 0; k < NITERS; k++) {
            const float lr = 0.05f / sqrtf(1.0f + (float)k);
            nbar_arrive(3);
            nbar_sync(4);
            u64 s = 0;
            {
                const ulonglong2* wv =
                    reinterpret_cast<const ulonglong2*>(&wIB[lane * 8]);
#pragma unroll
                for (int kk = 0; kk < 4; kk++) {
                    const ulonglong2 v = wv[kk];
                    add2(s, v.x);
                    add2(s, v.y);
                }
#pragma unroll
                for (int d = 16; d >= 1; d >>= 1)
                    add2(s, __shfl_xor_sync(FULL, s, d));
            }
            const float SI = upk_lo(s), SW = upk_hi(s);
            c   += lr * SW;
            eta -= lr * (1.0f - SI * (1.0f / (float)N_OBS));
            lam  = fmaxf(lam - lr * (delta - 1.0f + SI * (1.0f / (float)N_OBS)), 0.0f);
            if (lane == 0) { scB[0] = c; scB[1] = eta; scB[2] = lam; }
            project_warp8(partB, yhB, zB, lr, gamma);
        }
    }
    __syncthreads();

    if (tid < 128) {
        zout[sA * N_Y + tid] = zA[tid];
    } else if (tid < 256) {
        zout[sB * N_Y + (tid - 128)] = zB[tid - 128];
    }
}

// ---------------------------------------------------------------------------
extern "C" void kernel_launch(void* const* d_in, const int* in_sizes, int n_in,
                              void* d_out, int out_size) {
    const float* X     = (const float*)d_in[0];
    const float* Y     = (const float*)d_in[1];
    const float* W     = (const float*)d_in[2];
    const float* b     = (const float*)d_in[3];
    const float* delta = (const float*)d_in[4];
    const float* gamma = (const float*)d_in[5];

    float* out = (float*)d_out;
    float* zout = out;
    float* yhat;
    if (out_size >= 2 * N_OBS * N_Y) {
        yhat = out + N_OBS * N_Y;
    } else {
        void* p = nullptr;
        cudaGetSymbolAddress(&p, g_yhat_fallback);
        yhat = (float*)p;
    }

    prep_kernel<<<N_OBS, N_Y>>>(X, Y, W, b, yhat);
    solver_kernel<<<N_OBS / 2, NTHREADS>>>(yhat, delta, gamma, zout);
}